// round 1
// baseline (speedup 1.0000x reference)
#include <cuda_runtime.h>
#include <cstdint>

#define DIN  1024
#define DH   512
#define NB   8192
#define DOUT 512

#define MT 32            // rows per tile in recurrent kernel
#define KC 8             // k-chunk staged in smem
#define NCHUNK (DH / KC) // 64
#define REC_SMEM_BYTES ((2 * MT * DH + 2 * KC * DH) * 4)  // 163840

typedef unsigned long long ull;

// ---------------- scratch (static device allocations: allowed) ----------------
__device__ float g_sigma;
__device__ __align__(16) float g_Wt[DH * DH];     // Wt[k][n] = W[n][k]/sigma
__device__ __align__(16) float g_Wet[DIN * DH];   // Wet[d][j] = We[j][d]
__device__ __align__(16) float g_Wht[DH * DOUT];  // Wht[k][o] = Wh[o][k]
__device__ __align__(16) float g_xemb[NB * DH];
__device__ __align__(16) float g_h[NB * DH];

// ---------------- helpers ----------------
__device__ __forceinline__ ull pk2(float x, float y) {
    ull r;
    asm("mov.b64 %0, {%1,%2};" : "=l"(r) : "f"(x), "f"(y));
    return r;
}
__device__ __forceinline__ void upk2(ull a, float& x, float& y) {
    asm("mov.b64 {%0,%1}, %2;" : "=f"(x), "=f"(y) : "l"(a));
}
// packed fp32x2 FMA (Blackwell): 2x FFMA throughput
__device__ __forceinline__ ull fma2(ull a, ull b, ull c) {
    ull d;
    asm("fma.rn.f32x2 %0, %1, %2, %3;" : "=l"(d) : "l"(a), "l"(b), "l"(c));
    return d;
}
// accurate-enough tanh (~1e-6), immune to -use_fast_math lowering of tanhf
__device__ __forceinline__ float fast_tanh(float x) {
    float a = fabsf(x);
    float e = exp2f(-2.8853900817779268f * a);  // exp(-2a)
    float r = __fdividef(1.0f - e, 1.0f + e);
    return copysignf(r, x);
}

// ---------------- kernel 1: sigma = power-iteration spectral norm ----------------
__global__ void k_sigma(const float* __restrict__ W, const float* __restrict__ u) {
    __shared__ float sv[DH];
    __shared__ float red[DH];
    int t = threadIdx.x;  // 512 threads

    // tvec = W^T u  (column t)
    float acc = 0.f;
    for (int i = 0; i < DH; i++) acc += W[(size_t)i * DH + t] * u[i];
    sv[t] = acc;
    red[t] = acc * acc;
    __syncthreads();
    for (int s = 256; s > 0; s >>= 1) {
        if (t < s) red[t] += red[t + s];
        __syncthreads();
    }
    float inv1 = 1.f / (sqrtf(red[0]) + 1e-12f);
    __syncthreads();
    sv[t] *= inv1;  // v
    __syncthreads();
    // s = W v (row t)
    float sacc = 0.f;
    const float* wr = W + (size_t)t * DH;
    for (int j = 0; j < DH; j++) sacc += wr[j] * sv[j];
    red[t] = sacc * sacc;
    __syncthreads();
    for (int s = 256; s > 0; s >>= 1) {
        if (t < s) red[t] += red[t + s];
        __syncthreads();
    }
    if (t == 0) {
        float ss = red[0];
        g_sigma = ss / (sqrtf(ss) + 1e-12f);  // == u2 @ (W v) with the 1e-12 eps
    }
}

// ---------------- kernel 2: scaled/transposed weight prep ----------------
__global__ void k_prep(const float* __restrict__ W, const float* __restrict__ We,
                       const float* __restrict__ Wh) {
    float inv = 1.0f / g_sigma;
    int stride = gridDim.x * blockDim.x;
    int t0 = blockIdx.x * blockDim.x + threadIdx.x;
    for (int idx = t0; idx < DH * DH; idx += stride) {
        int k = idx >> 9, n = idx & 511;
        g_Wt[idx] = W[(size_t)n * DH + k] * inv;
    }
    for (int idx = t0; idx < DIN * DH; idx += stride) {
        int d = idx >> 9, j = idx & 511;
        g_Wet[idx] = We[(size_t)j * DIN + d];
    }
    for (int idx = t0; idx < DH * DOUT; idx += stride) {
        int k = idx / DOUT, o = idx - k * DOUT;
        g_Wht[idx] = Wh[(size_t)o * DH + k];
    }
}

// ---------------- generic tiled GEMM: C[M,N] = A[M,K] @ Bt[K,N] + bias ----------------
__global__ __launch_bounds__(256) void k_gemm(const float* __restrict__ A,
                                              const float* __restrict__ Bt,
                                              const float* __restrict__ bias,
                                              float* __restrict__ C, int M, int N, int K) {
    __shared__ float As[16][64];  // As[k][m]
    __shared__ float Bs[16][64];  // Bs[k][n]
    int tid = threadIdx.x;
    int bx = blockIdx.x;  // N tile
    int by = blockIdx.y;  // M tile
    int tx = tid & 15, ty = tid >> 4;
    float accv[4][4];
#pragma unroll
    for (int i = 0; i < 4; i++)
#pragma unroll
        for (int j = 0; j < 4; j++) accv[i][j] = 0.f;

    for (int k0 = 0; k0 < K; k0 += 16) {
        {
            int r = tid >> 2;
            int c = (tid & 3) * 4;
            float4 av = *(const float4*)&A[(size_t)(by * 64 + r) * K + k0 + c];
            As[c + 0][r] = av.x;
            As[c + 1][r] = av.y;
            As[c + 2][r] = av.z;
            As[c + 3][r] = av.w;
        }
        {
            int kr = tid >> 4;
            int c = (tid & 15) * 4;
            float4 bv = *(const float4*)&Bt[(size_t)(k0 + kr) * N + bx * 64 + c];
            *(float4*)&Bs[kr][c] = bv;
        }
        __syncthreads();
#pragma unroll
        for (int k = 0; k < 16; k++) {
            float a[4], b[4];
#pragma unroll
            for (int i = 0; i < 4; i++) a[i] = As[k][ty * 4 + i];
#pragma unroll
            for (int j = 0; j < 4; j++) b[j] = Bs[k][tx * 4 + j];
#pragma unroll
            for (int i = 0; i < 4; i++)
#pragma unroll
                for (int j = 0; j < 4; j++) accv[i][j] += a[i] * b[j];
        }
        __syncthreads();
    }
#pragma unroll
    for (int i = 0; i < 4; i++) {
        int m = by * 64 + ty * 4 + i;
#pragma unroll
        for (int j = 0; j < 4; j++) {
            int n = bx * 64 + tx * 4 + j;
            C[(size_t)m * N + n] = accv[i][j] + bias[n];
        }
    }
}

// ---------------- kernel 3: fused recurrent core ----------------
__device__ __forceinline__ void cp_chunk(const float* __restrict__ Wt, float* sh_w, int c,
                                         int buf, int tid) {
    const float4* src = (const float4*)(Wt + (size_t)c * KC * DH);
    unsigned sbase = (unsigned)__cvta_generic_to_shared(sh_w + (size_t)buf * KC * DH);
#pragma unroll
    for (int r = 0; r < 4; r++) {
        int e = tid + r * 256;  // float4 index within 8x512 chunk (1024 total)
        asm volatile("cp.async.cg.shared.global [%0], [%1], 16;" ::"r"(sbase + e * 16),
                     "l"(src + e));
    }
}

__global__ __launch_bounds__(256, 1) void k_recurrent(const float* __restrict__ bW,
                                                      const int* __restrict__ steps_p) {
    extern __shared__ float smem[];
    float* sh_hh = smem;                 // MT*DH
    float* sh_xeb = smem + MT * DH;      // MT*DH : x_emb + bW
    float* sh_w = smem + 2 * MT * DH;    // 2*KC*DH double buffer

    const int tid = threadIdx.x;
    const int tm = tid >> 6;   // 0..3
    const int tn = tid & 63;   // 0..63
    const int ncol0 = 2 * tn;  // + 128*j, pairs
    const int row0 = blockIdx.x * MT;
    const float* __restrict__ Wt = g_Wt;

    // load x_emb + bW tile
    for (int idx = tid; idx < MT * DH; idx += 256) {
        int n = idx & (DH - 1);
        sh_xeb[idx] = g_xemb[(size_t)row0 * DH + idx] + bW[n];
    }

    const float* hrow[8];
#pragma unroll
    for (int i = 0; i < 8; i++) hrow[i] = sh_hh + (size_t)(tm + 4 * i) * DH;

    float2 hreg[8][4];
#pragma unroll
    for (int i = 0; i < 8; i++)
#pragma unroll
        for (int j = 0; j < 4; j++) hreg[i][j] = make_float2(0.f, 0.f);

    const int steps = steps_p[0];
    __syncthreads();

    for (int s = 0; s < steps; s++) {
        // ---- inner iter 0 (hh starts at 0 => matmul term is 0) ----
#pragma unroll
        for (int i = 0; i < 8; i++) {
            float* hhrow = sh_hh + (size_t)(tm + 4 * i) * DH;
            const float* xerow = sh_xeb + (size_t)(tm + 4 * i) * DH;
#pragma unroll
            for (int j = 0; j < 4; j++) {
                int n0 = ncol0 + 128 * j;
                float2 xe = *(const float2*)(xerow + n0);
                float2 o;
                o.x = 0.5f * fast_tanh(hreg[i][j].x + xe.x);
                o.y = 0.5f * fast_tanh(hreg[i][j].y + xe.y);
                *(float2*)(hhrow + n0) = o;
            }
        }
        __syncthreads();

        // ---- inner iters 1..4 : hh = 0.5 hh + 0.5 tanh(hh@Wt + h + xeb) ----
        for (int it = 1; it < 5; it++) {
            ull acc2[8][4];
#pragma unroll
            for (int i = 0; i < 8; i++)
#pragma unroll
                for (int j = 0; j < 4; j++) acc2[i][j] = 0ull;

            cp_chunk(Wt, sh_w, 0, 0, tid);
            asm volatile("cp.async.commit_group;" ::: "memory");

            for (int c = 0; c < NCHUNK; c++) {
                asm volatile("cp.async.wait_group 0;" ::: "memory");
                __syncthreads();
                if (c + 1 < NCHUNK) {
                    cp_chunk(Wt, sh_w, c + 1, (c + 1) & 1, tid);
                    asm volatile("cp.async.commit_group;" ::: "memory");
                }
                const float* wb = sh_w + (size_t)(c & 1) * KC * DH;
                const int k0 = c * KC;
#pragma unroll
                for (int kk = 0; kk < KC; kk += 4) {
                    float4 a4[8];
#pragma unroll
                    for (int i = 0; i < 8; i++)
                        a4[i] = *(const float4*)(hrow[i] + k0 + kk);
#pragma unroll
                    for (int q = 0; q < 4; q++) {
                        ull a2[8];
#pragma unroll
                        for (int i = 0; i < 8; i++) {
                            float av = ((const float*)&a4[i])[q];
                            a2[i] = pk2(av, av);
                        }
                        const float* wrow = wb + (kk + q) * DH;
#pragma unroll
                        for (int j = 0; j < 4; j++) {
                            ull w2 = *(const ull*)(wrow + ncol0 + 128 * j);
#pragma unroll
                            for (int i = 0; i < 8; i++)
                                acc2[i][j] = fma2(a2[i], w2, acc2[i][j]);
                        }
                    }
                }
            }
            __syncthreads();  // all matmul reads of sh_hh complete

            // elementwise update of hh
#pragma unroll
            for (int i = 0; i < 8; i++) {
                float* hhrow = sh_hh + (size_t)(tm + 4 * i) * DH;
                const float* xerow = sh_xeb + (size_t)(tm + 4 * i) * DH;
#pragma unroll
                for (int j = 0; j < 4; j++) {
                    int n0 = ncol0 + 128 * j;
                    float ax, ay;
                    upk2(acc2[i][j], ax, ay);
                    float2 xe = *(const float2*)(xerow + n0);
                    float2 old = *(const float2*)(hhrow + n0);
                    float2 nv;
                    nv.x = 0.5f * old.x + 0.5f * fast_tanh(ax + hreg[i][j].x + xe.x);
                    nv.y = 0.5f * old.y + 0.5f * fast_tanh(ay + hreg[i][j].y + xe.y);
                    *(float2*)(hhrow + n0) = nv;
                }
            }
            __syncthreads();  // hh visible for next matmul
        }

        // ---- outer update: h = 0.5 h + 0.5 hh ----
#pragma unroll
        for (int i = 0; i < 8; i++) {
            const float* hhrow = sh_hh + (size_t)(tm + 4 * i) * DH;
#pragma unroll
            for (int j = 0; j < 4; j++) {
                int n0 = ncol0 + 128 * j;
                float2 hh = *(const float2*)(hhrow + n0);
                hreg[i][j].x = 0.5f * hreg[i][j].x + 0.5f * hh.x;
                hreg[i][j].y = 0.5f * hreg[i][j].y + 0.5f * hh.y;
            }
        }
        __syncthreads();
    }

    // store final h
#pragma unroll
    for (int i = 0; i < 8; i++) {
        int m = row0 + tm + 4 * i;
#pragma unroll
        for (int j = 0; j < 4; j++) {
            int n0 = ncol0 + 128 * j;
            *(float2*)&g_h[(size_t)m * DH + n0] = hreg[i][j];
        }
    }
}

// ---------------- launch ----------------
extern "C" void kernel_launch(void* const* d_in, const int* in_sizes, int n_in, void* d_out,
                              int out_size) {
    const float* x = (const float*)d_in[0];
    const float* We = (const float*)d_in[1];
    const float* be = (const float*)d_in[2];
    const float* W = (const float*)d_in[3];
    const float* bW = (const float*)d_in[4];
    const float* u = (const float*)d_in[5];
    const float* Wh = (const float*)d_in[6];
    const float* bh = (const float*)d_in[7];
    const int* steps = (const int*)d_in[8];
    float* out = (float*)d_out;

    float *p_Wet, *p_Wht, *p_xemb, *p_h;
    cudaGetSymbolAddress((void**)&p_Wet, g_Wet);
    cudaGetSymbolAddress((void**)&p_Wht, g_Wht);
    cudaGetSymbolAddress((void**)&p_xemb, g_xemb);
    cudaGetSymbolAddress((void**)&p_h, g_h);

    cudaFuncSetAttribute(k_recurrent, cudaFuncAttributeMaxDynamicSharedMemorySize,
                         REC_SMEM_BYTES);

    k_sigma<<<1, 512>>>(W, u);
    k_prep<<<512, 256>>>(W, We, Wh);

    dim3 g1(DH / 64, NB / 64);
    k_gemm<<<g1, 256>>>(x, p_Wet, be, p_xemb, NB, DH, DIN);

    k_recurrent<<<NB / MT, 256, REC_SMEM_BYTES>>>(bW, steps);

    dim3 g2(DOUT / 64, NB / 64);
    k_gemm<<<g2, 256>>>(p_h, p_Wht, bh, out, NB, DOUT, DH);
}

// round 2
// speedup vs baseline: 1.0003x; 1.0003x over previous
#include <cuda_runtime.h>
#include <cstdint>

#define DIN  1024
#define DH   512
#define NB   8192
#define DOUT 512

#define MT 32            // rows per tile in recurrent kernel
#define KC 8             // k-chunk staged in smem
#define NCHUNK (DH / KC) // 64
#define REC_SMEM_BYTES ((2 * MT * DH + 2 * KC * DH) * 4)  // 163840

typedef unsigned long long ull;

// ---------------- scratch (static device allocations: allowed) ----------------
__device__ float g_sigma;
__device__ __align__(16) float g_Wt[DH * DH];     // Wt[k][n] = W[n][k]/sigma
__device__ __align__(16) float g_Wet[DIN * DH];   // Wet[d][j] = We[j][d]
__device__ __align__(16) float g_Wht[DH * DOUT];  // Wht[k][o] = Wh[o][k]
__device__ __align__(16) float g_xemb[NB * DH];
__device__ __align__(16) float g_h[NB * DH];

// ---------------- helpers ----------------
__device__ __forceinline__ ull pk2(float x, float y) {
    ull r;
    asm("mov.b64 %0, {%1,%2};" : "=l"(r) : "f"(x), "f"(y));
    return r;
}
__device__ __forceinline__ void upk2(ull a, float& x, float& y) {
    asm("mov.b64 {%0,%1}, %2;" : "=f"(x), "=f"(y) : "l"(a));
}
// packed fp32x2 FMA (Blackwell): 2x FFMA throughput
__device__ __forceinline__ ull fma2(ull a, ull b, ull c) {
    ull d;
    asm("fma.rn.f32x2 %0, %1, %2, %3;" : "=l"(d) : "l"(a), "l"(b), "l"(c));
    return d;
}
// accurate-enough tanh (~1e-6), immune to -use_fast_math lowering of tanhf
__device__ __forceinline__ float fast_tanh(float x) {
    float a = fabsf(x);
    float e = exp2f(-2.8853900817779268f * a);  // exp(-2a)
    float r = __fdividef(1.0f - e, 1.0f + e);
    return copysignf(r, x);
}

// ---------------- kernel 1: sigma = power-iteration spectral norm ----------------
__global__ void k_sigma(const float* __restrict__ W, const float* __restrict__ u) {
    __shared__ float sv[DH];
    __shared__ float red[DH];
    int t = threadIdx.x;  // 512 threads

    // tvec = W^T u  (column t)
    float acc = 0.f;
    for (int i = 0; i < DH; i++) acc += W[(size_t)i * DH + t] * u[i];
    sv[t] = acc;
    red[t] = acc * acc;
    __syncthreads();
    for (int s = 256; s > 0; s >>= 1) {
        if (t < s) red[t] += red[t + s];
        __syncthreads();
    }
    float inv1 = 1.f / (sqrtf(red[0]) + 1e-12f);
    __syncthreads();
    sv[t] *= inv1;  // v
    __syncthreads();
    // s = W v (row t)
    float sacc = 0.f;
    const float* wr = W + (size_t)t * DH;
    for (int j = 0; j < DH; j++) sacc += wr[j] * sv[j];
    red[t] = sacc * sacc;
    __syncthreads();
    for (int s = 256; s > 0; s >>= 1) {
        if (t < s) red[t] += red[t + s];
        __syncthreads();
    }
    if (t == 0) {
        float ss = red[0];
        g_sigma = ss / (sqrtf(ss) + 1e-12f);  // == u2 @ (W v) with the 1e-12 eps
    }
}

// ---------------- kernel 2: scaled/transposed weight prep ----------------
__global__ void k_prep(const float* __restrict__ W, const float* __restrict__ We,
                       const float* __restrict__ Wh) {
    float inv = 1.0f / g_sigma;
    int stride = gridDim.x * blockDim.x;
    int t0 = blockIdx.x * blockDim.x + threadIdx.x;
    for (int idx = t0; idx < DH * DH; idx += stride) {
        int k = idx >> 9, n = idx & 511;
        g_Wt[idx] = W[(size_t)n * DH + k] * inv;
    }
    for (int idx = t0; idx < DIN * DH; idx += stride) {
        int d = idx >> 9, j = idx & 511;
        g_Wet[idx] = We[(size_t)j * DIN + d];
    }
    for (int idx = t0; idx < DH * DOUT; idx += stride) {
        int k = idx / DOUT, o = idx - k * DOUT;
        g_Wht[idx] = Wh[(size_t)o * DH + k];
    }
}

// ---------------- generic tiled GEMM: C[M,N] = A[M,K] @ Bt[K,N] + bias ----------------
__global__ __launch_bounds__(256) void k_gemm(const float* __restrict__ A,
                                              const float* __restrict__ Bt,
                                              const float* __restrict__ bias,
                                              float* __restrict__ C, int M, int N, int K) {
    __shared__ float As[16][64];  // As[k][m]
    __shared__ float Bs[16][64];  // Bs[k][n]
    int tid = threadIdx.x;
    int bx = blockIdx.x;  // N tile
    int by = blockIdx.y;  // M tile
    int tx = tid & 15, ty = tid >> 4;
    float accv[4][4];
#pragma unroll
    for (int i = 0; i < 4; i++)
#pragma unroll
        for (int j = 0; j < 4; j++) accv[i][j] = 0.f;

    for (int k0 = 0; k0 < K; k0 += 16) {
        {
            int r = tid >> 2;
            int c = (tid & 3) * 4;
            float4 av = *(const float4*)&A[(size_t)(by * 64 + r) * K + k0 + c];
            As[c + 0][r] = av.x;
            As[c + 1][r] = av.y;
            As[c + 2][r] = av.z;
            As[c + 3][r] = av.w;
        }
        {
            int kr = tid >> 4;
            int c = (tid & 15) * 4;
            float4 bv = *(const float4*)&Bt[(size_t)(k0 + kr) * N + bx * 64 + c];
            *(float4*)&Bs[kr][c] = bv;
        }
        __syncthreads();
#pragma unroll
        for (int k = 0; k < 16; k++) {
            float a[4], b[4];
#pragma unroll
            for (int i = 0; i < 4; i++) a[i] = As[k][ty * 4 + i];
#pragma unroll
            for (int j = 0; j < 4; j++) b[j] = Bs[k][tx * 4 + j];
#pragma unroll
            for (int i = 0; i < 4; i++)
#pragma unroll
                for (int j = 0; j < 4; j++) accv[i][j] += a[i] * b[j];
        }
        __syncthreads();
    }
#pragma unroll
    for (int i = 0; i < 4; i++) {
        int m = by * 64 + ty * 4 + i;
#pragma unroll
        for (int j = 0; j < 4; j++) {
            int n = bx * 64 + tx * 4 + j;
            C[(size_t)m * N + n] = accv[i][j] + bias[n];
        }
    }
}

// ---------------- kernel 3: fused recurrent core ----------------
__device__ __forceinline__ void cp_chunk(const float* __restrict__ Wt, float* sh_w, int c,
                                         int buf, int tid) {
    const float4* src = (const float4*)(Wt + (size_t)c * KC * DH);
    unsigned sbase = (unsigned)__cvta_generic_to_shared(sh_w + (size_t)buf * KC * DH);
#pragma unroll
    for (int r = 0; r < 4; r++) {
        int e = tid + r * 256;  // float4 index within 8x512 chunk (1024 total)
        asm volatile("cp.async.cg.shared.global [%0], [%1], 16;" ::"r"(sbase + e * 16),
                     "l"(src + e));
    }
}

__global__ __launch_bounds__(256, 1) void k_recurrent(const float* __restrict__ bW,
                                                      const int* __restrict__ steps_p) {
    extern __shared__ float smem[];
    float* sh_hh = smem;                 // MT*DH
    float* sh_xeb = smem + MT * DH;      // MT*DH : x_emb + bW
    float* sh_w = smem + 2 * MT * DH;    // 2*KC*DH double buffer

    const int tid = threadIdx.x;
    const int tm = tid >> 6;   // 0..3
    const int tn = tid & 63;   // 0..63
    const int ncol0 = 2 * tn;  // + 128*j, pairs
    const int row0 = blockIdx.x * MT;
    const float* __restrict__ Wt = g_Wt;

    // load x_emb + bW tile
    for (int idx = tid; idx < MT * DH; idx += 256) {
        int n = idx & (DH - 1);
        sh_xeb[idx] = g_xemb[(size_t)row0 * DH + idx] + bW[n];
    }

    const float* hrow[8];
#pragma unroll
    for (int i = 0; i < 8; i++) hrow[i] = sh_hh + (size_t)(tm + 4 * i) * DH;

    float2 hreg[8][4];
#pragma unroll
    for (int i = 0; i < 8; i++)
#pragma unroll
        for (int j = 0; j < 4; j++) hreg[i][j] = make_float2(0.f, 0.f);

    const int steps = steps_p[0];
    __syncthreads();

    for (int s = 0; s < steps; s++) {
        // ---- inner iter 0 (hh starts at 0 => matmul term is 0) ----
#pragma unroll
        for (int i = 0; i < 8; i++) {
            float* hhrow = sh_hh + (size_t)(tm + 4 * i) * DH;
            const float* xerow = sh_xeb + (size_t)(tm + 4 * i) * DH;
#pragma unroll
            for (int j = 0; j < 4; j++) {
                int n0 = ncol0 + 128 * j;
                float2 xe = *(const float2*)(xerow + n0);
                float2 o;
                o.x = 0.5f * fast_tanh(hreg[i][j].x + xe.x);
                o.y = 0.5f * fast_tanh(hreg[i][j].y + xe.y);
                *(float2*)(hhrow + n0) = o;
            }
        }
        __syncthreads();

        // ---- inner iters 1..4 : hh = 0.5 hh + 0.5 tanh(hh@Wt + h + xeb) ----
        for (int it = 1; it < 5; it++) {
            ull acc2[8][4];
#pragma unroll
            for (int i = 0; i < 8; i++)
#pragma unroll
                for (int j = 0; j < 4; j++) acc2[i][j] = 0ull;

            cp_chunk(Wt, sh_w, 0, 0, tid);
            asm volatile("cp.async.commit_group;" ::: "memory");

            for (int c = 0; c < NCHUNK; c++) {
                asm volatile("cp.async.wait_group 0;" ::: "memory");
                __syncthreads();
                if (c + 1 < NCHUNK) {
                    cp_chunk(Wt, sh_w, c + 1, (c + 1) & 1, tid);
                    asm volatile("cp.async.commit_group;" ::: "memory");
                }
                const float* wb = sh_w + (size_t)(c & 1) * KC * DH;
                const int k0 = c * KC;
#pragma unroll
                for (int kk = 0; kk < KC; kk += 4) {
                    float4 a4[8];
#pragma unroll
                    for (int i = 0; i < 8; i++)
                        a4[i] = *(const float4*)(hrow[i] + k0 + kk);
#pragma unroll
                    for (int q = 0; q < 4; q++) {
                        ull a2[8];
#pragma unroll
                        for (int i = 0; i < 8; i++) {
                            float av = ((const float*)&a4[i])[q];
                            a2[i] = pk2(av, av);
                        }
                        const float* wrow = wb + (kk + q) * DH;
#pragma unroll
                        for (int j = 0; j < 4; j++) {
                            ull w2 = *(const ull*)(wrow + ncol0 + 128 * j);
#pragma unroll
                            for (int i = 0; i < 8; i++)
                                acc2[i][j] = fma2(a2[i], w2, acc2[i][j]);
                        }
                    }
                }
            }
            __syncthreads();  // all matmul reads of sh_hh complete

            // elementwise update of hh
#pragma unroll
            for (int i = 0; i < 8; i++) {
                float* hhrow = sh_hh + (size_t)(tm + 4 * i) * DH;
                const float* xerow = sh_xeb + (size_t)(tm + 4 * i) * DH;
#pragma unroll
                for (int j = 0; j < 4; j++) {
                    int n0 = ncol0 + 128 * j;
                    float ax, ay;
                    upk2(acc2[i][j], ax, ay);
                    float2 xe = *(const float2*)(xerow + n0);
                    float2 old = *(const float2*)(hhrow + n0);
                    float2 nv;
                    nv.x = 0.5f * old.x + 0.5f * fast_tanh(ax + hreg[i][j].x + xe.x);
                    nv.y = 0.5f * old.y + 0.5f * fast_tanh(ay + hreg[i][j].y + xe.y);
                    *(float2*)(hhrow + n0) = nv;
                }
            }
            __syncthreads();  // hh visible for next matmul
        }

        // ---- outer update: h = 0.5 h + 0.5 hh ----
#pragma unroll
        for (int i = 0; i < 8; i++) {
            const float* hhrow = sh_hh + (size_t)(tm + 4 * i) * DH;
#pragma unroll
            for (int j = 0; j < 4; j++) {
                int n0 = ncol0 + 128 * j;
                float2 hh = *(const float2*)(hhrow + n0);
                hreg[i][j].x = 0.5f * hreg[i][j].x + 0.5f * hh.x;
                hreg[i][j].y = 0.5f * hreg[i][j].y + 0.5f * hh.y;
            }
        }
        __syncthreads();
    }

    // store final h
#pragma unroll
    for (int i = 0; i < 8; i++) {
        int m = row0 + tm + 4 * i;
#pragma unroll
        for (int j = 0; j < 4; j++) {
            int n0 = ncol0 + 128 * j;
            *(float2*)&g_h[(size_t)m * DH + n0] = hreg[i][j];
        }
    }
}

// ---------------- launch ----------------
extern "C" void kernel_launch(void* const* d_in, const int* in_sizes, int n_in, void* d_out,
                              int out_size) {
    const float* x = (const float*)d_in[0];
    const float* We = (const float*)d_in[1];
    const float* be = (const float*)d_in[2];
    const float* W = (const float*)d_in[3];
    const float* bW = (const float*)d_in[4];
    const float* u = (const float*)d_in[5];
    const float* Wh = (const float*)d_in[6];
    const float* bh = (const float*)d_in[7];
    const int* steps = (const int*)d_in[8];
    float* out = (float*)d_out;

    float *p_Wet, *p_Wht, *p_xemb, *p_h;
    cudaGetSymbolAddress((void**)&p_Wet, g_Wet);
    cudaGetSymbolAddress((void**)&p_Wht, g_Wht);
    cudaGetSymbolAddress((void**)&p_xemb, g_xemb);
    cudaGetSymbolAddress((void**)&p_h, g_h);

    cudaFuncSetAttribute(k_recurrent, cudaFuncAttributeMaxDynamicSharedMemorySize,
                         REC_SMEM_BYTES);

    k_sigma<<<1, 512>>>(W, u);
    k_prep<<<512, 256>>>(W, We, Wh);

    dim3 g1(DH / 64, NB / 64);
    k_gemm<<<g1, 256>>>(x, p_Wet, be, p_xemb, NB, DH, DIN);

    k_recurrent<<<NB / MT, 256, REC_SMEM_BYTES>>>(bW, steps);

    dim3 g2(DOUT / 64, NB / 64);
    k_gemm<<<g2, 256>>>(p_h, p_Wht, bh, out, NB, DOUT, DH);
}